// round 2
// baseline (speedup 1.0000x reference)
#include <cuda_runtime.h>

// Problem shape (fixed by the reference): ze [16,2048,512] fp32, codebook [8192,512] fp32.
// M = 32768 tokens, K = 8192 codes, D = 512.
#define M_TOT 32768
#define K_TOT 8192
#define D_DIM 512

#define BM 128
#define BN 128
#define BK 32
#define LDT (BM + 4)   // 132: padded smem row, float4-aligned, breaks worst conflicts

// Scratch (no allocations allowed -> device globals)
__device__ float g_hn[K_TOT];    // 0.5 * ||c_k||^2
__device__ int   g_idx[M_TOT];   // argmin index per token

// Packed fp32x2 FMA (Blackwell full-rate fp32 path; plain FFMA is half rate on B300)
__device__ __forceinline__ float2 ffma2(float2 a, float2 b, float2 c) {
    float2 d;
    asm("fma.rn.f32x2 %0, %1, %2, %3;"
        : "=l"(*reinterpret_cast<unsigned long long*>(&d))
        : "l"(*reinterpret_cast<unsigned long long*>(&a)),
          "l"(*reinterpret_cast<unsigned long long*>(&b)),
          "l"(*reinterpret_cast<unsigned long long*>(&c)));
    return d;
}

// ---------------------------------------------------------------------------
// Kernel 1: half-norms of codebook rows. One warp per code.
// Grid: K_TOT/8 blocks x 8 warps  => exactly 8192 warps (was 1/8 of that: BUG).
// ---------------------------------------------------------------------------
__global__ void norm_kernel(const float* __restrict__ cb) {
    int warp = (blockIdx.x * blockDim.x + threadIdx.x) >> 5;
    int lane = threadIdx.x & 31;
    if (warp >= K_TOT) return;
    const float4* row = reinterpret_cast<const float4*>(cb + (size_t)warp * D_DIM);
    float s = 0.0f;
#pragma unroll
    for (int t = 0; t < 4; ++t) {
        float4 v = row[lane + 32 * t];
        s += v.x * v.x + v.y * v.y + v.z * v.z + v.w * v.w;
    }
#pragma unroll
    for (int off = 16; off > 0; off >>= 1)
        s += __shfl_xor_sync(0xffffffffu, s, off);
    if (lane == 0) g_hn[warp] = 0.5f * s;
}

// ---------------------------------------------------------------------------
// Kernel 2: fused GEMM + argmin.
// Each block: 128 tokens x ALL 8192 codes, accumulating over D=512.
// score s = z.c - 0.5||c||^2 ; argmin dist == argmax s.
// ---------------------------------------------------------------------------
__global__ __launch_bounds__(256, 2)
void vq_argmin_kernel(const float* __restrict__ A,   // ze   [M_TOT, D]
                      const float* __restrict__ Bc)  // code [K_TOT, D]
{
    __shared__ float As[BK][LDT];   // [d][m]
    __shared__ float Bs[BK][LDT];   // [d][k]
    __shared__ float hns[BN];

    const int tid = threadIdx.x;
    const int tx  = tid & 15;       // column-group lane (codes)
    const int ty  = tid >> 4;       // row-group (tokens)
    const int ty8 = ty * 8;
    const int tx8 = tx * 8;
    const int m0  = blockIdx.x * BM;

    const int lcol  = tid & 31;     // d index within tile (coalesced dim)
    const int lrow0 = tid >> 5;     // 0..7

    float best[8];
    int   bidx[8];
#pragma unroll
    for (int i = 0; i < 8; ++i) { best[i] = -1e30f; bidx[i] = 0; }

    for (int n0 = 0; n0 < K_TOT; n0 += BN) {
        __syncthreads();                       // protect hns + smem from prior epilogue
        if (tid < BN) hns[tid] = g_hn[n0 + tid];

        float2 acc[8][4];
#pragma unroll
        for (int i = 0; i < 8; ++i)
#pragma unroll
            for (int j = 0; j < 4; ++j) acc[i][j] = make_float2(0.0f, 0.0f);

        for (int d0 = 0; d0 < D_DIM; d0 += BK) {
            __syncthreads();                   // previous compute done before overwrite
#pragma unroll
            for (int p = 0; p < 16; ++p) {
                int r = lrow0 + p * 8;
                As[lcol][r] = A [(size_t)(m0 + r) * D_DIM + d0 + lcol];
                Bs[lcol][r] = Bc[(size_t)(n0 + r) * D_DIM + d0 + lcol];
            }
            __syncthreads();

#pragma unroll
            for (int kk = 0; kk < BK; ++kk) {
                float4 a0 = *reinterpret_cast<const float4*>(&As[kk][ty8]);
                float4 a1 = *reinterpret_cast<const float4*>(&As[kk][ty8 + 4]);
                float4 b0 = *reinterpret_cast<const float4*>(&Bs[kk][tx8]);
                float4 b1 = *reinterpret_cast<const float4*>(&Bs[kk][tx8 + 4]);
                float2 bp[4] = { make_float2(b0.x, b0.y), make_float2(b0.z, b0.w),
                                 make_float2(b1.x, b1.y), make_float2(b1.z, b1.w) };
                float  av[8] = { a0.x, a0.y, a0.z, a0.w, a1.x, a1.y, a1.z, a1.w };
#pragma unroll
                for (int i = 0; i < 8; ++i) {
                    float2 ad = make_float2(av[i], av[i]);
#pragma unroll
                    for (int j = 0; j < 4; ++j)
                        acc[i][j] = ffma2(ad, bp[j], acc[i][j]);
                }
            }
        }

        // Epilogue: update running best. Ascending k order => strict '>' keeps
        // the lowest index on ties (matches jnp.argmin).
#pragma unroll
        for (int i = 0; i < 8; ++i) {
#pragma unroll
            for (int j = 0; j < 4; ++j) {
                int   kc = n0 + tx8 + 2 * j;
                float s0 = acc[i][j].x - hns[tx8 + 2 * j];
                float s1 = acc[i][j].y - hns[tx8 + 2 * j + 1];
                if (s0 > best[i]) { best[i] = s0; bidx[i] = kc; }
                if (s1 > best[i]) { best[i] = s1; bidx[i] = kc + 1; }
            }
        }
    }

    // Reduce across the 16 column-lanes sharing the same 8 token rows.
    // lane = (ty&1)*16 + tx, so xor offsets 8,4,2,1 stay inside each 16-lane half.
#pragma unroll
    for (int off = 8; off > 0; off >>= 1) {
#pragma unroll
        for (int i = 0; i < 8; ++i) {
            float os = __shfl_xor_sync(0xffffffffu, best[i], off);
            int   oi = __shfl_xor_sync(0xffffffffu, bidx[i], off);
            if (os > best[i] || (os == best[i] && oi < bidx[i])) {
                best[i] = os; bidx[i] = oi;
            }
        }
    }
    if (tx == 0) {
#pragma unroll
        for (int i = 0; i < 8; ++i)
            g_idx[m0 + ty8 + i] = bidx[i];
    }
}

// ---------------------------------------------------------------------------
// Kernel 3: gather winning codebook rows to the output.
// ---------------------------------------------------------------------------
__global__ void gather_kernel(const float* __restrict__ cb, float* __restrict__ out) {
    int m = blockIdx.x;
    int k = g_idx[m];
    const float4* src = reinterpret_cast<const float4*>(cb + (size_t)k * D_DIM);
    float4*       dst = reinterpret_cast<float4*>(out + (size_t)m * D_DIM);
    dst[threadIdx.x] = src[threadIdx.x];   // 128 threads x float4 = 512 floats
}

// ---------------------------------------------------------------------------
extern "C" void kernel_launch(void* const* d_in, const int* in_sizes, int n_in,
                              void* d_out, int out_size) {
    const float* ze = (const float*)d_in[0];   // [16,2048,512]
    const float* cb = (const float*)d_in[1];   // [8192,512]
    float* out = (float*)d_out;

    norm_kernel<<<K_TOT / 8, 256>>>(cb);         // 1024 blocks * 8 warps = 8192 warps (1/code)
    vq_argmin_kernel<<<M_TOT / BM, 256>>>(ze, cb);   // 256 blocks
    gather_kernel<<<M_TOT, 128>>>(cb, out);          // 32768 blocks
}

// round 4
// speedup vs baseline: 1.2477x; 1.2477x over previous
#include <cuda_runtime.h>
#include <cstdint>

#define M_TOT 32768
#define K_TOT 8192
#define D_DIM 512

// CTA tile 128(M) x 256(N), BK=16. 8 warps of 64x64. 3-stage cp.async pipeline.
#define BM 128
#define BN 256
#define BK 16
#define LDK 20                 // padded row stride (floats): conflict-free frag loads
#define STG_FLTS 15360         // per stage: A hi/lo 128*20*2 + B hi/lo 256*20*2
#define OFF_ALO 2560
#define OFF_BHI 5120
#define OFF_BLO 10240
#define SCR_OFF 46080          // 3*STG_FLTS (floats): merge scratch
#define SMEM_BYTES (SCR_OFF * 4 + 4096)
#define TILES 1024             // 32 groups * 32 k-tiles per M-tile

// ---- device scratch --------------------------------------------------------
__device__ float g_hn[K_TOT];
__device__ int   g_idx[M_TOT];
__device__ float g_Ahi[M_TOT * D_DIM];
__device__ float g_Alo[M_TOT * D_DIM];
__device__ float g_Bhi[K_TOT * D_DIM];
__device__ float g_Blo[K_TOT * D_DIM];

// ---- helpers ---------------------------------------------------------------
__device__ __forceinline__ uint32_t smem_u32(const void* p) {
    uint32_t a;
    asm("{ .reg .u64 t; cvta.to.shared.u64 t, %1; cvt.u32.u64 %0, t; }" : "=r"(a) : "l"(p));
    return a;
}
__device__ __forceinline__ float tf32_rna(float f) {
    uint32_t u;
    asm("cvt.rna.tf32.f32 %0, %1;" : "=r"(u) : "f"(f));
    return __uint_as_float(u);
}
__device__ __forceinline__ void cp16(uint32_t dst, const float* src) {
    asm volatile("cp.async.cg.shared.global [%0], [%1], 16;" :: "r"(dst), "l"(src) : "memory");
}
#define CP_COMMIT() asm volatile("cp.async.commit_group;" ::: "memory")
#define CP_WAIT1()  asm volatile("cp.async.wait_group 1;" ::: "memory")
#define CP_WAIT0()  asm volatile("cp.async.wait_group 0;" ::: "memory")

// Legacy tensor-core path: mma.sync m16n8k8 tf32 (sm_80+ PTX, valid on plain sm_103)
__device__ __forceinline__ void mma8(float* c, const uint32_t a[4], uint32_t b0, uint32_t b1) {
    asm volatile(
        "mma.sync.aligned.m16n8k8.row.col.f32.tf32.tf32.f32 "
        "{%0,%1,%2,%3}, {%4,%5,%6,%7}, {%8,%9}, {%0,%1,%2,%3};"
        : "+f"(c[0]), "+f"(c[1]), "+f"(c[2]), "+f"(c[3])
        : "r"(a[0]), "r"(a[1]), "r"(a[2]), "r"(a[3]), "r"(b0), "r"(b1));
}

// ---- prep kernels ----------------------------------------------------------
__global__ void pack_ze(const float* __restrict__ ze) {
    int i = blockIdx.x * blockDim.x + threadIdx.x;
    float f = ze[i];
    float hi = tf32_rna(f);
    g_Ahi[i] = hi;
    g_Alo[i] = tf32_rna(f - hi);
}
__global__ void pack_cb(const float* __restrict__ cb) {
    int i = blockIdx.x * blockDim.x + threadIdx.x;
    float f = cb[i];
    float hi = tf32_rna(f);
    g_Bhi[i] = hi;
    g_Blo[i] = tf32_rna(f - hi);
}
__global__ void norm_kernel(const float* __restrict__ cb) {
    int warp = (blockIdx.x * blockDim.x + threadIdx.x) >> 5;
    int lane = threadIdx.x & 31;
    const float4* row = reinterpret_cast<const float4*>(cb + (size_t)warp * D_DIM);
    float s = 0.0f;
#pragma unroll
    for (int t = 0; t < 4; ++t) {
        float4 v = row[lane + 32 * t];
        s += v.x * v.x + v.y * v.y + v.z * v.z + v.w * v.w;
    }
#pragma unroll
    for (int off = 16; off > 0; off >>= 1) s += __shfl_xor_sync(0xffffffffu, s, off);
    if (lane == 0) g_hn[warp] = 0.5f * s;
}

// ---- main fused GEMM + argmin ----------------------------------------------
__global__ void __launch_bounds__(256, 1) vq_mma_kernel() {
    extern __shared__ float smem_f[];
    const uint32_t sbase = smem_u32(smem_f);
    const uint32_t* su = reinterpret_cast<const uint32_t*>(smem_f);

    const int tid  = threadIdx.x;
    const int wid  = tid >> 5, lane = tid & 31;
    const int wm   = wid & 1;            // m half (64 rows)
    const int wn   = wid >> 1;           // n quarter (64 cols)
    const int q    = lane >> 2;          // 0..7
    const int r4   = lane & 3;           // 0..3

    float* s_sb = smem_f + SCR_OFF;                       // [128][4]
    int*   s_si = reinterpret_cast<int*>(smem_f + SCR_OFF + 512);

    for (int half_i = 0; half_i < 2; ++half_i) {
        const int mt = blockIdx.x + half_i * 128;
        const int m0 = mt * BM;

        float acc[4][8][4];
        float bestv[4][2];
        int   besti[4][2];
#pragma unroll
        for (int mf = 0; mf < 4; ++mf) {
#pragma unroll
            for (int h = 0; h < 2; ++h) { bestv[mf][h] = -3.0e38f; besti[mf][h] = 0; }
#pragma unroll
            for (int nf = 0; nf < 8; ++nf)
#pragma unroll
                for (int c = 0; c < 4; ++c) acc[mf][nf][c] = 0.0f;
        }

        // ---- stage loader: tile t = (g<<5)|kt ----
        auto issue_tile = [&](int t) {
            const int g = t >> 5, kt = t & 31;
            const uint32_t stg = sbase + (uint32_t)(t % 3) * (STG_FLTS * 4);
#pragma unroll
            for (int i = 0; i < 2; ++i) {                 // A: 512 segs hi + lo
                int seg = tid + i * 256;
                int row = seg >> 2, sk = seg & 3;
                uint32_t d = stg + (uint32_t)(row * LDK + sk * 4) * 4;
                size_t soff = (size_t)(m0 + row) * D_DIM + kt * BK + sk * 4;
                cp16(d, g_Ahi + soff);
                cp16(d + OFF_ALO * 4, g_Alo + soff);
            }
#pragma unroll
            for (int i = 0; i < 4; ++i) {                 // B: 1024 segs hi + lo
                int seg = tid + i * 256;
                int row = seg >> 2, sk = seg & 3;
                uint32_t d = stg + (uint32_t)(OFF_BHI + row * LDK + sk * 4) * 4;
                size_t soff = (size_t)(g * BN + row) * D_DIM + kt * BK + sk * 4;
                cp16(d, g_Bhi + soff);
                cp16(d + (OFF_BLO - OFF_BHI) * 4, g_Blo + soff);
            }
            CP_COMMIT();
        };

        issue_tile(0);
        issue_tile(1);

        for (int t = 0; t < TILES; ++t) {
            if (t < TILES - 1) { CP_WAIT1(); } else { CP_WAIT0(); }
            __syncthreads();
            if (t + 2 < TILES) issue_tile(t + 2);

            const uint32_t* st = su + (t % 3) * STG_FLTS;
            const uint32_t* sAh = st;
            const uint32_t* sAl = st + OFF_ALO;
            const uint32_t* sBh = st + OFF_BHI;
            const uint32_t* sBl = st + OFF_BLO;

#pragma unroll
            for (int ks = 0; ks < BK; ks += 8) {
                uint32_t ah[4][4], al[4][4];
#pragma unroll
                for (int mf = 0; mf < 4; ++mf) {
                    int rb = (wm * 64 + mf * 16 + q) * LDK + ks + r4;
                    ah[mf][0] = sAh[rb];          al[mf][0] = sAl[rb];
                    ah[mf][1] = sAh[rb + 8*LDK];  al[mf][1] = sAl[rb + 8*LDK];
                    ah[mf][2] = sAh[rb + 4];      al[mf][2] = sAl[rb + 4];
                    ah[mf][3] = sAh[rb + 8*LDK+4];al[mf][3] = sAl[rb + 8*LDK+4];
                }
#pragma unroll
                for (int nf = 0; nf < 8; ++nf) {
                    int nb = (wn * 64 + nf * 8 + q) * LDK + ks + r4;
                    uint32_t bh0 = sBh[nb], bh1 = sBh[nb + 4];
                    uint32_t bl0 = sBl[nb], bl1 = sBl[nb + 4];
#pragma unroll
                    for (int mf = 0; mf < 4; ++mf) {
                        mma8(acc[mf][nf], ah[mf], bh0, bh1);   // hi*hi
                        mma8(acc[mf][nf], ah[mf], bl0, bl1);   // hi*lo
                        mma8(acc[mf][nf], al[mf], bh0, bh1);   // lo*hi
                    }
                }
            }

            if ((t & 31) == 31) {                   // group done: fold into running argmax
                const int g = t >> 5;
#pragma unroll
                for (int nf = 0; nf < 8; ++nf) {
                    int gc = g * BN + wn * 64 + nf * 8 + 2 * r4;
                    float h0 = __ldg(&g_hn[gc]), h1 = __ldg(&g_hn[gc + 1]);
#pragma unroll
                    for (int mf = 0; mf < 4; ++mf) {
                        float s0 = acc[mf][nf][0] - h0, s1 = acc[mf][nf][1] - h1;
                        float s2 = acc[mf][nf][2] - h0, s3 = acc[mf][nf][3] - h1;
                        if (s0 > bestv[mf][0]) { bestv[mf][0] = s0; besti[mf][0] = gc; }
                        if (s1 > bestv[mf][0]) { bestv[mf][0] = s1; besti[mf][0] = gc + 1; }
                        if (s2 > bestv[mf][1]) { bestv[mf][1] = s2; besti[mf][1] = gc; }
                        if (s3 > bestv[mf][1]) { bestv[mf][1] = s3; besti[mf][1] = gc + 1; }
                        acc[mf][nf][0] = 0.0f; acc[mf][nf][1] = 0.0f;
                        acc[mf][nf][2] = 0.0f; acc[mf][nf][3] = 0.0f;
                    }
                }
            }
        }

        // Merge the 4 lanes (r4) holding the same rows.
#pragma unroll
        for (int off = 1; off <= 2; off <<= 1) {
#pragma unroll
            for (int mf = 0; mf < 4; ++mf)
#pragma unroll
                for (int h = 0; h < 2; ++h) {
                    float ov = __shfl_xor_sync(0xffffffffu, bestv[mf][h], off);
                    int   oi = __shfl_xor_sync(0xffffffffu, besti[mf][h], off);
                    if (ov > bestv[mf][h] || (ov == bestv[mf][h] && oi < besti[mf][h])) {
                        bestv[mf][h] = ov; besti[mf][h] = oi;
                    }
                }
        }
        if (r4 == 0) {
#pragma unroll
            for (int mf = 0; mf < 4; ++mf)
#pragma unroll
                for (int h = 0; h < 2; ++h) {
                    int rl = wm * 64 + mf * 16 + h * 8 + q;
                    s_sb[rl * 4 + wn] = bestv[mf][h];
                    s_si[rl * 4 + wn] = besti[mf][h];
                }
        }
        __syncthreads();
        if (tid < BM) {
            float bv = s_sb[tid * 4]; int bi = s_si[tid * 4];
#pragma unroll
            for (int w = 1; w < 4; ++w) {
                float ov = s_sb[tid * 4 + w]; int oi = s_si[tid * 4 + w];
                if (ov > bv || (ov == bv && oi < bi)) { bv = ov; bi = oi; }
            }
            g_idx[m0 + tid] = bi;
        }
        __syncthreads();
    }
}

// ---- gather -----------------------------------------------------------------
__global__ void gather_kernel(const float* __restrict__ cb, float* __restrict__ out) {
    int m = blockIdx.x;
    int k = g_idx[m];
    const float4* src = reinterpret_cast<const float4*>(cb + (size_t)k * D_DIM);
    float4*       dst = reinterpret_cast<float4*>(out + (size_t)m * D_DIM);
    dst[threadIdx.x] = src[threadIdx.x];
}

// ---- entry ------------------------------------------------------------------
extern "C" void kernel_launch(void* const* d_in, const int* in_sizes, int n_in,
                              void* d_out, int out_size) {
    const float* ze = (const float*)d_in[0];
    const float* cb = (const float*)d_in[1];
    float* out = (float*)d_out;

    cudaFuncSetAttribute(vq_mma_kernel, cudaFuncAttributeMaxDynamicSharedMemorySize, SMEM_BYTES);

    pack_ze<<<(M_TOT * D_DIM) / 256, 256>>>(ze);
    pack_cb<<<(K_TOT * D_DIM) / 256, 256>>>(cb);
    norm_kernel<<<K_TOT / 8, 256>>>(cb);
    vq_mma_kernel<<<128, 256, SMEM_BYTES>>>();
    gather_kernel<<<M_TOT, 128>>>(cb, out);
}

// round 5
// speedup vs baseline: 1.5118x; 1.2117x over previous
#include <cuda_runtime.h>
#include <cstdint>

#define M_TOT 32768
#define K_TOT 8192
#define D_DIM 512

// CTA tile 128(M) x 256(N), BK=16; 16 warps of 32x64; 3-stage pipeline.
#define BM 128
#define BN 256
#define TILES 1024                 // 32 groups * 32 k-tiles
#define A_TILE_WORDS 4096          // 16KB: 8 mblk * 2 kc * 32 lanes * (ah4|al4)
#define B_TILE_WORDS 8192          // 32KB: 32 nblk * 2 kc * 32 lanes * (bh2|bl2)
#define STG_WORDS 12288            // 48KB
#define SCR_WORDS (3 * STG_WORDS)
#define SMEM_BYTES (SCR_WORDS * 4 + 4096)

// ---- device scratch ----------------------------------------------------------
__device__ float g_hn[K_TOT];
__device__ int   g_idx[M_TOT];
__device__ float g_A[M_TOT * D_DIM * 2];   // 128MB fragment-packed hi|lo
__device__ float g_B[K_TOT * D_DIM * 2];   //  32MB fragment-packed hi|lo

// ---- helpers -------------------------------------------------------------------
__device__ __forceinline__ uint32_t smem_u32(const void* p) {
    uint32_t a;
    asm("{ .reg .u64 t; cvta.to.shared.u64 t, %1; cvt.u32.u64 %0, t; }" : "=r"(a) : "l"(p));
    return a;
}
__device__ __forceinline__ float tf32_rna(float f) {
    uint32_t u;
    asm("cvt.rna.tf32.f32 %0, %1;" : "=r"(u) : "f"(f));
    return __uint_as_float(u);
}
__device__ __forceinline__ void cp16(uint32_t dst, const float* src) {
    asm volatile("cp.async.cg.shared.global [%0], [%1], 16;" :: "r"(dst), "l"(src) : "memory");
}
#define CP_COMMIT() asm volatile("cp.async.commit_group;" ::: "memory")
#define CP_WAIT1()  asm volatile("cp.async.wait_group 1;" ::: "memory")
#define CP_WAIT0()  asm volatile("cp.async.wait_group 0;" ::: "memory")

__device__ __forceinline__ void mma8(float* c, const uint4& a, uint32_t b0, uint32_t b1) {
    asm volatile(
        "mma.sync.aligned.m16n8k8.row.col.f32.tf32.tf32.f32 "
        "{%0,%1,%2,%3}, {%4,%5,%6,%7}, {%8,%9}, {%0,%1,%2,%3};"
        : "+f"(c[0]), "+f"(c[1]), "+f"(c[2]), "+f"(c[3])
        : "r"(a.x), "r"(a.y), "r"(a.z), "r"(a.w), "r"(b0), "r"(b1));
}

// ---- prep kernels: split to tf32 hi/lo AND permute into mma fragment order ----
// A frag (m16n8k8): a_j at (row q + 8*(j&1), col r4 + 4*(j>>1)), lane = q*4+r4.
__global__ void pack_ze(const float* __restrict__ ze) {
    int i = blockIdx.x * blockDim.x + threadIdx.x;
    float f = ze[i];
    float hi = tf32_rna(f);
    float lo = tf32_rna(f - hi);
    int m = i >> 9, d = i & 511;
    int mt = m >> 7, mr = m & 127, blk = mr >> 4, rowq = mr & 7, rhalf = (mr >> 3) & 1;
    int kt = d >> 4, kk = d & 15, kc = kk >> 3, kr = kk & 7, r4 = kr & 3, khalf = kr >> 2;
    int lane = rowq * 4 + r4, j = khalf * 2 + rhalf;
    size_t base = ((size_t)(mt * 32 + kt)) * A_TILE_WORDS + (size_t)((blk * 2 + kc) * 32 + lane) * 8;
    g_A[base + j]     = hi;
    g_A[base + 4 + j] = lo;
}
// B frag: b_j at (k = r4 + 4*j, n = q), lane = q*4+r4. Layout per lane: [bh0,bh1,bl0,bl1].
__global__ void pack_cb(const float* __restrict__ cb) {
    int i = blockIdx.x * blockDim.x + threadIdx.x;
    float f = cb[i];
    float hi = tf32_rna(f);
    float lo = tf32_rna(f - hi);
    int n = i >> 9, d = i & 511;
    int g = n >> 8, nr = n & 255, nblk = nr >> 3, q = nr & 7;
    int kt = d >> 4, kk = d & 15, kc = kk >> 3, kr = kk & 7, r4 = kr & 3, khalf = kr >> 2;
    int lane = q * 4 + r4;
    size_t base = ((size_t)(g * 32 + kt)) * B_TILE_WORDS + (size_t)((nblk * 2 + kc) * 32 + lane) * 4;
    g_B[base + khalf]     = hi;
    g_B[base + 2 + khalf] = lo;
}
__global__ void norm_kernel(const float* __restrict__ cb) {
    int warp = (blockIdx.x * blockDim.x + threadIdx.x) >> 5;
    int lane = threadIdx.x & 31;
    const float4* row = reinterpret_cast<const float4*>(cb + (size_t)warp * D_DIM);
    float s = 0.0f;
#pragma unroll
    for (int t = 0; t < 4; ++t) {
        float4 v = row[lane + 32 * t];
        s += v.x * v.x + v.y * v.y + v.z * v.z + v.w * v.w;
    }
#pragma unroll
    for (int off = 16; off > 0; off >>= 1) s += __shfl_xor_sync(0xffffffffu, s, off);
    if (lane == 0) g_hn[warp] = 0.5f * s;
}

// ---- main fused GEMM + argmin ---------------------------------------------------
__global__ void __launch_bounds__(512, 1) vq_mma_kernel() {
    extern __shared__ float smem_f[];
    const uint32_t sbase = smem_u32(smem_f);

    const int tid  = threadIdx.x;
    const int wid  = tid >> 5, lane = tid & 31;
    const int wm   = wid >> 2;          // 0..3 : 32-row group
    const int wn   = wid & 3;           // 0..3 : 64-col group
    const int q    = lane >> 2;         // 0..7
    const int r4   = lane & 3;          // 0..3
    const int m0   = blockIdx.x * BM;

    float* s_sb = smem_f + SCR_WORDS;
    int*   s_si = reinterpret_cast<int*>(smem_f + SCR_WORDS + 512);

    float acc[2][8][4];
    float bestv[2][2];
    int   besti[2][2];
#pragma unroll
    for (int mf = 0; mf < 2; ++mf) {
#pragma unroll
        for (int h = 0; h < 2; ++h) { bestv[mf][h] = -3.0e38f; besti[mf][h] = 0; }
#pragma unroll
        for (int nf = 0; nf < 8; ++nf)
#pragma unroll
            for (int c = 0; c < 4; ++c) acc[mf][nf][c] = 0.0f;
    }

    auto issue_tile = [&](int t) {
        const uint32_t stw = sbase + (uint32_t)(t % 3) * (STG_WORDS * 4);
        const float* aG = g_A + ((size_t)(blockIdx.x * 32) + (t & 31)) * A_TILE_WORDS;
        const float* bG = g_B + ((size_t)((t >> 5) * 32 + (t & 31))) * B_TILE_WORDS;
#pragma unroll
        for (int i = 0; i < 2; ++i) {              // A: 1024 x 16B
            int seg = tid + i * 512;
            cp16(stw + seg * 16, aG + seg * 4);
        }
#pragma unroll
        for (int i = 0; i < 4; ++i) {              // B: 2048 x 16B
            int seg = tid + i * 512;
            cp16(stw + A_TILE_WORDS * 4 + seg * 16, bG + seg * 4);
        }
        CP_COMMIT();
    };

    issue_tile(0);
    issue_tile(1);

    for (int t = 0; t < TILES; ++t) {
        if (t < TILES - 1) { CP_WAIT1(); } else { CP_WAIT0(); }
        __syncthreads();
        if (t + 2 < TILES) issue_tile(t + 2);

        const float* st = smem_f + (t % 3) * STG_WORDS;
#pragma unroll
        for (int kc = 0; kc < 2; ++kc) {
            uint4 ah[2], al[2];
#pragma unroll
            for (int mf = 0; mf < 2; ++mf) {
                const uint4* pa = reinterpret_cast<const uint4*>(
                    st + (size_t)(((wm * 2 + mf) * 2 + kc) * 32 + lane) * 8);
                ah[mf] = pa[0];
                al[mf] = pa[1];
            }
#pragma unroll
            for (int nf = 0; nf < 8; ++nf) {
                uint4 b = *reinterpret_cast<const uint4*>(
                    st + A_TILE_WORDS + (size_t)(((wn * 8 + nf) * 2 + kc) * 32 + lane) * 4);
#pragma unroll
                for (int mf = 0; mf < 2; ++mf) {
                    mma8(acc[mf][nf], ah[mf], b.x, b.y);   // hi*hi
                    mma8(acc[mf][nf], ah[mf], b.z, b.w);   // hi*lo
                    mma8(acc[mf][nf], al[mf], b.x, b.y);   // lo*hi
                }
            }
        }

        if ((t & 31) == 31) {                        // group finished: fold argmax
            const int g = t >> 5;
#pragma unroll
            for (int nf = 0; nf < 8; ++nf) {
                int gc = g * BN + wn * 64 + nf * 8 + 2 * r4;
                float h0 = __ldg(&g_hn[gc]), h1 = __ldg(&g_hn[gc + 1]);
#pragma unroll
                for (int mf = 0; mf < 2; ++mf) {
                    float s0 = acc[mf][nf][0] - h0, s1 = acc[mf][nf][1] - h1;
                    float s2 = acc[mf][nf][2] - h0, s3 = acc[mf][nf][3] - h1;
                    if (s0 > bestv[mf][0]) { bestv[mf][0] = s0; besti[mf][0] = gc; }
                    if (s1 > bestv[mf][0]) { bestv[mf][0] = s1; besti[mf][0] = gc + 1; }
                    if (s2 > bestv[mf][1]) { bestv[mf][1] = s2; besti[mf][1] = gc; }
                    if (s3 > bestv[mf][1]) { bestv[mf][1] = s3; besti[mf][1] = gc + 1; }
                    acc[mf][nf][0] = 0.0f; acc[mf][nf][1] = 0.0f;
                    acc[mf][nf][2] = 0.0f; acc[mf][nf][3] = 0.0f;
                }
            }
        }
    }

    // Merge 4 lanes sharing rows (lane = q*4 + r4; xor 1,2 stay within the quad).
#pragma unroll
    for (int off = 1; off <= 2; off <<= 1) {
#pragma unroll
        for (int mf = 0; mf < 2; ++mf)
#pragma unroll
            for (int h = 0; h < 2; ++h) {
                float ov = __shfl_xor_sync(0xffffffffu, bestv[mf][h], off);
                int   oi = __shfl_xor_sync(0xffffffffu, besti[mf][h], off);
                if (ov > bestv[mf][h] || (ov == bestv[mf][h] && oi < besti[mf][h])) {
                    bestv[mf][h] = ov; besti[mf][h] = oi;
                }
            }
    }
    if (r4 == 0) {
#pragma unroll
        for (int mf = 0; mf < 2; ++mf)
#pragma unroll
            for (int h = 0; h < 2; ++h) {
                int rl = wm * 32 + mf * 16 + h * 8 + q;
                s_sb[rl * 4 + wn] = bestv[mf][h];
                s_si[rl * 4 + wn] = besti[mf][h];
            }
    }
    __syncthreads();
    if (tid < BM) {
        float bv = s_sb[tid * 4]; int bi = s_si[tid * 4];
#pragma unroll
        for (int w = 1; w < 4; ++w) {
            float ov = s_sb[tid * 4 + w]; int oi = s_si[tid * 4 + w];
            if (ov > bv || (ov == bv && oi < bi)) { bv = ov; bi = oi; }
        }
        g_idx[m0 + tid] = bi;
    }
}

// ---- gather ----------------------------------------------------------------------
__global__ void gather_kernel(const float* __restrict__ cb, float* __restrict__ out) {
    int m = blockIdx.x;
    int k = g_idx[m];
    const float4* src = reinterpret_cast<const float4*>(cb + (size_t)k * D_DIM);
    float4*       dst = reinterpret_cast<float4*>(out + (size_t)m * D_DIM);
    dst[threadIdx.x] = src[threadIdx.x];
}

// ---- entry -----------------------------------------------------------------------
extern "C" void kernel_launch(void* const* d_in, const int* in_sizes, int n_in,
                              void* d_out, int out_size) {
    const float* ze = (const float*)d_in[0];
    const float* cb = (const float*)d_in[1];
    float* out = (float*)d_out;

    cudaFuncSetAttribute(vq_mma_kernel, cudaFuncAttributeMaxDynamicSharedMemorySize, SMEM_BYTES);

    pack_ze<<<(M_TOT * D_DIM) / 256, 256>>>(ze);
    pack_cb<<<(K_TOT * D_DIM) / 256, 256>>>(cb);
    norm_kernel<<<K_TOT / 8, 256>>>(cb);
    vq_mma_kernel<<<M_TOT / BM, 512, SMEM_BYTES>>>();
    gather_kernel<<<M_TOT, 128>>>(cb, out);
}

// round 6
// speedup vs baseline: 1.6974x; 1.1228x over previous
#include <cuda_runtime.h>
#include <cuda_fp16.h>
#include <cstdint>

#define M_TOT 32768
#define K_TOT 8192
#define D_DIM 512

// CTA tile 128(M) x 256(N), BK=16; 16 warps of 32x64; fp16 hi/lo split, 4-term.
#define BM 128
#define BN 256
#define TILES 1024                    // 32 groups * 32 k-tiles
#define A_TILE_HALF 4096              // 8KB : 8 mblk * 32 lanes * 16 halves
#define B_TILE_HALF 8192              // 16KB: 32 nblk * 32 lanes * 8 halves
#define STG_BYTES 24576               // 8KB A + 16KB B
#define NSTG 3
#define SCR_BYTES (NSTG * STG_BYTES)  // 73728
#define SMEM_BYTES (SCR_BYTES + 4096)

// ---- device scratch -----------------------------------------------------------
__device__ float  g_hn[K_TOT];
__device__ int    g_idx[M_TOT];
__device__ __half g_A[(size_t)M_TOT * D_DIM * 2];   // 64MB fragment-packed hi|lo
__device__ __half g_B[(size_t)K_TOT * D_DIM * 2];   // 16MB fragment-packed hi|lo (L2-resident)

// ---- helpers --------------------------------------------------------------------
__device__ __forceinline__ uint32_t smem_u32(const void* p) {
    uint32_t a;
    asm("{ .reg .u64 t; cvta.to.shared.u64 t, %1; cvt.u32.u64 %0, t; }" : "=r"(a) : "l"(p));
    return a;
}
__device__ __forceinline__ void cp16(uint32_t dst, const void* src) {
    asm volatile("cp.async.cg.shared.global [%0], [%1], 16;" :: "r"(dst), "l"(src) : "memory");
}
#define CP_COMMIT() asm volatile("cp.async.commit_group;" ::: "memory")
#define CP_WAIT1()  asm volatile("cp.async.wait_group 1;" ::: "memory")
#define CP_WAIT0()  asm volatile("cp.async.wait_group 0;" ::: "memory")

__device__ __forceinline__ void mma16(float* c, const uint4& a, uint32_t b0, uint32_t b1) {
    asm volatile(
        "mma.sync.aligned.m16n8k16.row.col.f32.f16.f16.f32 "
        "{%0,%1,%2,%3}, {%4,%5,%6,%7}, {%8,%9}, {%0,%1,%2,%3};"
        : "+f"(c[0]), "+f"(c[1]), "+f"(c[2]), "+f"(c[3])
        : "r"(a.x), "r"(a.y), "r"(a.z), "r"(a.w), "r"(b0), "r"(b1));
}

// ---- prep: fp16 hi/lo split + permute into m16n8k16 fragment order --------------
// lane = q*4 + r4. A element (row, k): q=row&7, rhalf=row>>3 (within 16-row blk),
// k: par=k&1, r4=(k>>1)&3, khalf=k>>3; reg = rhalf + 2*khalf; half idx = reg*2+par.
__global__ void pack_ze(const float* __restrict__ ze) {
    int i = blockIdx.x * blockDim.x + threadIdx.x;
    float f = ze[i];
    __half hi = __float2half_rn(f);
    __half lo = __float2half_rn(f - __half2float(hi));
    int m = i >> 9, d = i & 511;
    int mt = m >> 7, mr = m & 127, mblk = mr >> 4, row = mr & 15;
    int q = row & 7, rhalf = row >> 3;
    int kt = d >> 4, kk = d & 15, par = kk & 1, r4 = (kk >> 1) & 3, khalf = kk >> 3;
    int lane = q * 4 + r4, reg = rhalf + 2 * khalf;
    size_t base = ((size_t)(mt * 32 + kt)) * A_TILE_HALF + (size_t)(mblk * 32 + lane) * 16;
    g_A[base + reg * 2 + par]     = hi;
    g_A[base + 8 + reg * 2 + par] = lo;
}
// B element (col n, k): q = n&7 (groupID), k: par=k&1, r4=(k>>1)&3, khalf=k>>3 (reg).
__global__ void pack_cb(const float* __restrict__ cb) {
    int i = blockIdx.x * blockDim.x + threadIdx.x;
    float f = cb[i];
    __half hi = __float2half_rn(f);
    __half lo = __float2half_rn(f - __half2float(hi));
    int n = i >> 9, d = i & 511;
    int g = n >> 8, nr = n & 255, nblk = nr >> 3, q = nr & 7;
    int kt = d >> 4, kk = d & 15, par = kk & 1, r4 = (kk >> 1) & 3, khalf = kk >> 3;
    int lane = q * 4 + r4;
    size_t base = ((size_t)(g * 32 + kt)) * B_TILE_HALF + (size_t)(nblk * 32 + lane) * 8;
    g_B[base + khalf * 2 + par]     = hi;
    g_B[base + 4 + khalf * 2 + par] = lo;
}
__global__ void norm_kernel(const float* __restrict__ cb) {
    int warp = (blockIdx.x * blockDim.x + threadIdx.x) >> 5;
    int lane = threadIdx.x & 31;
    const float4* row = reinterpret_cast<const float4*>(cb + (size_t)warp * D_DIM);
    float s = 0.0f;
#pragma unroll
    for (int t = 0; t < 4; ++t) {
        float4 v = row[lane + 32 * t];
        s += v.x * v.x + v.y * v.y + v.z * v.z + v.w * v.w;
    }
#pragma unroll
    for (int off = 16; off > 0; off >>= 1) s += __shfl_xor_sync(0xffffffffu, s, off);
    if (lane == 0) g_hn[warp] = 0.5f * s;
}

// ---- main fused GEMM + argmin ----------------------------------------------------
__global__ void __launch_bounds__(512, 2) vq_mma_kernel() {
    extern __shared__ __align__(16) char smem[];
    const uint32_t sbase = smem_u32(smem);

    const int tid  = threadIdx.x;
    const int wid  = tid >> 5, lane = tid & 31;
    const int wm   = wid >> 2;          // 0..3 : 32-row group
    const int wn   = wid & 3;           // 0..3 : 64-col group
    const int q    = lane >> 2;         // 0..7
    const int r4   = lane & 3;          // 0..3
    const int m0   = blockIdx.x * BM;

    float* s_sb = reinterpret_cast<float*>(smem + SCR_BYTES);
    int*   s_si = reinterpret_cast<int*>(smem + SCR_BYTES + 2048);

    float acc[2][8][4];
    float bestv[2][2];
    int   besti[2][2];
#pragma unroll
    for (int mf = 0; mf < 2; ++mf) {
#pragma unroll
        for (int h = 0; h < 2; ++h) { bestv[mf][h] = -3.0e38f; besti[mf][h] = 0; }
#pragma unroll
        for (int nf = 0; nf < 8; ++nf)
#pragma unroll
            for (int c = 0; c < 4; ++c) acc[mf][nf][c] = 0.0f;
    }

    auto issue_tile = [&](int t) {
        const uint32_t stw = sbase + (uint32_t)(t % NSTG) * STG_BYTES;
        const __half* aG = g_A + ((size_t)(blockIdx.x * 32) + (t & 31)) * A_TILE_HALF;
        const __half* bG = g_B + ((size_t)((t >> 5) * 32 + (t & 31))) * B_TILE_HALF;
        // A: 512 x 16B segs
        cp16(stw + tid * 16, aG + tid * 8);
        // B: 1024 x 16B segs
#pragma unroll
        for (int i = 0; i < 2; ++i) {
            int seg = tid + i * 512;
            cp16(stw + 8192 + seg * 16, bG + seg * 8);
        }
        CP_COMMIT();
    };

    issue_tile(0);
    issue_tile(1);

    for (int t = 0; t < TILES; ++t) {
        if (t < TILES - 1) { CP_WAIT1(); } else { CP_WAIT0(); }
        __syncthreads();
        if (t + 2 < TILES) issue_tile(t + 2);

        const char* st = smem + (t % NSTG) * STG_BYTES;

        uint4 ah[2], al[2];
#pragma unroll
        for (int mf = 0; mf < 2; ++mf) {
            const uint4* pa = reinterpret_cast<const uint4*>(
                st + (size_t)((wm * 2 + mf) * 32 + lane) * 32);
            ah[mf] = pa[0];
            al[mf] = pa[1];
        }
#pragma unroll
        for (int nf = 0; nf < 8; ++nf) {
            uint4 b = *reinterpret_cast<const uint4*>(
                st + 8192 + (size_t)((wn * 8 + nf) * 32 + lane) * 16);
#pragma unroll
            for (int mf = 0; mf < 2; ++mf) {
                mma16(acc[mf][nf], ah[mf], b.x, b.y);   // hi*hi
                mma16(acc[mf][nf], ah[mf], b.z, b.w);   // hi*lo
                mma16(acc[mf][nf], al[mf], b.x, b.y);   // lo*hi
                mma16(acc[mf][nf], al[mf], b.z, b.w);   // lo*lo
            }
        }

        if ((t & 31) == 31) {                         // group done: fold argmax
            const int g = t >> 5;
#pragma unroll
            for (int nf = 0; nf < 8; ++nf) {
                int gc = g * BN + wn * 64 + nf * 8 + 2 * r4;
                float h0 = __ldg(&g_hn[gc]), h1 = __ldg(&g_hn[gc + 1]);
#pragma unroll
                for (int mf = 0; mf < 2; ++mf) {
                    float s0 = acc[mf][nf][0] - h0, s1 = acc[mf][nf][1] - h1;
                    float s2 = acc[mf][nf][2] - h0, s3 = acc[mf][nf][3] - h1;
                    if (s0 > bestv[mf][0]) { bestv[mf][0] = s0; besti[mf][0] = gc; }
                    if (s1 > bestv[mf][0]) { bestv[mf][0] = s1; besti[mf][0] = gc + 1; }
                    if (s2 > bestv[mf][1]) { bestv[mf][1] = s2; besti[mf][1] = gc; }
                    if (s3 > bestv[mf][1]) { bestv[mf][1] = s3; besti[mf][1] = gc + 1; }
                    acc[mf][nf][0] = 0.0f; acc[mf][nf][1] = 0.0f;
                    acc[mf][nf][2] = 0.0f; acc[mf][nf][3] = 0.0f;
                }
            }
        }
    }

    // Merge the 4 lanes of each quad (lane = q*4 + r4; xor 1,2 stay in-quad).
#pragma unroll
    for (int off = 1; off <= 2; off <<= 1) {
#pragma unroll
        for (int mf = 0; mf < 2; ++mf)
#pragma unroll
            for (int h = 0; h < 2; ++h) {
                float ov = __shfl_xor_sync(0xffffffffu, bestv[mf][h], off);
                int   oi = __shfl_xor_sync(0xffffffffu, besti[mf][h], off);
                if (ov > bestv[mf][h] || (ov == bestv[mf][h] && oi < besti[mf][h])) {
                    bestv[mf][h] = ov; besti[mf][h] = oi;
                }
            }
    }
    if (r4 == 0) {
#pragma unroll
        for (int mf = 0; mf < 2; ++mf)
#pragma unroll
            for (int h = 0; h < 2; ++h) {
                int rl = wm * 32 + mf * 16 + h * 8 + q;
                s_sb[rl * 4 + wn] = bestv[mf][h];
                s_si[rl * 4 + wn] = besti[mf][h];
            }
    }
    __syncthreads();
    if (tid < BM) {
        float bv = s_sb[tid * 4]; int bi = s_si[tid * 4];
#pragma unroll
        for (int w = 1; w < 4; ++w) {
            float ov = s_sb[tid * 4 + w]; int oi = s_si[tid * 4 + w];
            if (ov > bv || (ov == bv && oi < bi)) { bv = ov; bi = oi; }
        }
        g_idx[m0 + tid] = bi;
    }
}

// ---- gather ------------------------------------------------------------------------
__global__ void gather_kernel(const float* __restrict__ cb, float* __restrict__ out) {
    int m = blockIdx.x;
    int k = g_idx[m];
    const float4* src = reinterpret_cast<const float4*>(cb + (size_t)k * D_DIM);
    float4*       dst = reinterpret_cast<float4*>(out + (size_t)m * D_DIM);
    dst[threadIdx.x] = src[threadIdx.x];
}

// ---- entry ---------------------------------------------------------------------------
extern "C" void kernel_launch(void* const* d_in, const int* in_sizes, int n_in,
                              void* d_out, int out_size) {
    const float* ze = (const float*)d_in[0];
    const float* cb = (const float*)d_in[1];
    float* out = (float*)d_out;

    cudaFuncSetAttribute(vq_mma_kernel, cudaFuncAttributeMaxDynamicSharedMemorySize, SMEM_BYTES);

    pack_ze<<<(M_TOT * D_DIM) / 256, 256>>>(ze);
    pack_cb<<<(K_TOT * D_DIM) / 256, 256>>>(cb);
    norm_kernel<<<K_TOT / 8, 256>>>(cb);
    vq_mma_kernel<<<M_TOT / BM, 512, SMEM_BYTES>>>();
    gather_kernel<<<M_TOT, 128>>>(cb, out);
}